// round 15
// baseline (speedup 1.0000x reference)
#include <cuda_runtime.h>
#include <cstdint>

// WanRotaryPosEmbedS2VStyle: build (freqs_cos, freqs_sin) grids.
//
//   output: cos (1, n_tok, 1, 128) then sin; n_tok = F*3600.
//   Per token (f,y,x): ch [0,44)=t_tab[pt], [44,86)=h_tab[y], [86,128)=w_tab[x].
//
// R15: last untested store-side lever — Blackwell 256-bit stores
// (st.global.v8.f32, sm_100+). Same R3 work shape (19800 warps, 4 tokens
// each) but each lane owns 8 channels and the warp covers 2 tokens per store
// instruction (lane>>4 = token parity): 4x STG.256 per warp instead of
// 8x STG.128 — half the store instructions/transactions for the same bytes.

#define T_DIM 44
#define H_DIM 42
#define W_DIM 42
#define GRID_W 60
#define GRID_HW 3600
#define FIXED_REF 30
#define X_PER 4            // tokens per warp (divides 60)

__device__ __forceinline__ void stg256(float* p,
                                       float a0, float a1, float a2, float a3,
                                       float a4, float a5, float a6, float a7)
{
    asm volatile(
        "st.global.v8.f32 [%0], {%1, %2, %3, %4, %5, %6, %7, %8};"
        :: "l"(p), "f"(a0), "f"(a1), "f"(a2), "f"(a3),
           "f"(a4), "f"(a5), "f"(a6), "f"(a7)
        : "memory");
}

__global__ __launch_bounds__(256)
void wan_rope_kernel(
    const float* __restrict__ tcos, const float* __restrict__ hcos,
    const float* __restrict__ wcos, const float* __restrict__ tsin,
    const float* __restrict__ hsin, const float* __restrict__ wsin,
    const int*   __restrict__ nvf_p,
    float* __restrict__ out, int n_tok, int n_warps)
{
    const int gtid = blockIdx.x * blockDim.x + threadIdx.x;
    const int w    = gtid >> 5;
    if (w >= n_warps) return;
    const int lane = gtid & 31;
    const int tp   = lane >> 4;            // token parity (0/1) within the warp
    const int d0   = (lane & 15) << 3;     // channels [d0, d0+8)

    const int tok0 = w * X_PER;            // 4 tokens, same (f,y) row
    const int f    = tok0 / GRID_HW;
    const int rem  = tok0 - f * GRID_HW;
    const int y    = rem / GRID_W;
    const int x0   = rem - y * GRID_W;

    const int video_pp = __ldg(nvf_p);
    const int pt = (f < video_pp) ? f : FIXED_REF;

    const int tbase = pt * T_DIM;
    const int hbase = y * H_DIM - T_DIM;
    const int wbase = (x0 + tp) * W_DIM - (T_DIM + H_DIM);  // this lane's token

    // 4 even pairs per lane: d = d0, d0+2, d0+4, d0+6 (each pair in one table)
    const float* pc[4];
    const float* ps[4];
    bool   isw[4];
    float2 c[4], s[4];
#pragma unroll
    for (int p = 0; p < 4; p++) {
        const int d = d0 + 2 * p;
        if (d < T_DIM)              { pc[p] = tcos + tbase + d; ps[p] = tsin + tbase + d; isw[p] = false; }
        else if (d < T_DIM + H_DIM) { pc[p] = hcos + hbase + d; ps[p] = hsin + hbase + d; isw[p] = false; }
        else                        { pc[p] = wcos + wbase + d; ps[p] = wsin + wbase + d; isw[p] = true;  }
        c[p] = __ldg(reinterpret_cast<const float2*>(pc[p]));
        s[p] = __ldg(reinterpret_cast<const float2*>(ps[p]));
    }

    float* oc = out + (size_t)(tok0 + tp) * 128 + d0;
    float* os = oc + (size_t)n_tok * 128;

    // tokens (tok0+tp): one STG.256 for cos, one for sin (warp covers 2 tokens)
    stg256(oc, c[0].x, c[0].y, c[1].x, c[1].y, c[2].x, c[2].y, c[3].x, c[3].y);
    stg256(os, s[0].x, s[0].y, s[1].x, s[1].y, s[2].x, s[2].y, s[3].x, s[3].y);

    // tokens (tok0+2+tp): only w-pairs change (x += 2), base+imm loads
#pragma unroll
    for (int p = 0; p < 4; p++) {
        if (isw[p]) {
            c[p] = __ldg(reinterpret_cast<const float2*>(pc[p] + 2 * W_DIM));
            s[p] = __ldg(reinterpret_cast<const float2*>(ps[p] + 2 * W_DIM));
        }
    }
    stg256(oc + 256, c[0].x, c[0].y, c[1].x, c[1].y, c[2].x, c[2].y, c[3].x, c[3].y);
    stg256(os + 256, s[0].x, s[0].y, s[1].x, s[1].y, s[2].x, s[2].y, s[3].x, s[3].y);
}

extern "C" void kernel_launch(void* const* d_in, const int* in_sizes, int n_in,
                              void* d_out, int out_size)
{
    // 0: hidden_states (unused)
    // 1: freq_t_cos  2: freq_h_cos  3: freq_w_cos
    // 4: freq_t_sin  5: freq_h_sin  6: freq_w_sin
    // 7: num_video_frames (int32)   8: num_ref_frames (int32)
    const float* tcos = (const float*)d_in[1];
    const float* hcos = (const float*)d_in[2];
    const float* wcos = (const float*)d_in[3];
    const float* tsin = (const float*)d_in[4];
    const float* hsin = (const float*)d_in[5];
    const float* wsin = (const float*)d_in[6];
    const int*   nvf  = (const int*)d_in[7];

    float* out = (float*)d_out;

    const int n_tok   = out_size / 256;    // out_size = 2 * n_tok * 128
    const int n_warps = n_tok / X_PER;     // 3600 % 4 == 0
    const int threads = 256;
    const int blocks  = (n_warps * 32 + threads - 1) / threads;

    wan_rope_kernel<<<blocks, threads>>>(tcos, hcos, wcos, tsin, hsin, wsin,
                                         nvf, out, n_tok, n_warps);
}

// round 16
// speedup vs baseline: 1.1404x; 1.1404x over previous
#include <cuda_runtime.h>
#include <cstdint>

// WanRotaryPosEmbedS2VStyle: build (freqs_cos, freqs_sin) grids.
//
//   output: cos (1, n_tok, 1, 128) then sin; n_tok = F*3600.
//   Per token (f,y,x): ch [0,44)=t_tab[pt], [44,86)=h_tab[y], [86,128)=w_tab[x].
//
// FINAL (R16 = R3, best measured: bench 14.848us, ncu 14.336us, rel_err 0).
// Fifteen rounds of evidence: the kernel is bounded by the 81MB output store
// stream through L1tex/L2 at ~5.7 TB/s (store-sector rate; ~half the
// combined LTS cap). Independently varied with no effect beyond noise:
// instruction count (4.8M -> 1.3M), load removal (FMA rotation), occupancy/
// waves (X_PER 1..20), predication, base+imm addressing, STG.256, and the
// SMEM+cp.async.bulk (TMA) store path (both bulk variants regressed 35%+).
// Structure: each warp owns 4 consecutive x-tokens (same f,y); index math +
// t/h table loads once per warp; per extra token only w-lanes (d>=86) reload
// via predicated LDG.64; 2x STG.128 per token, perfectly coalesced.

#define T_DIM 44
#define H_DIM 42
#define W_DIM 42
#define GRID_W 60
#define GRID_HW 3600
#define FIXED_REF 30
#define X_PER 4            // tokens per warp (divides 60) — measured optimum

__global__ void wan_rope_kernel(
    const float* __restrict__ tcos, const float* __restrict__ hcos,
    const float* __restrict__ wcos, const float* __restrict__ tsin,
    const float* __restrict__ hsin, const float* __restrict__ wsin,
    const int*   __restrict__ nvf_p,
    float* __restrict__ out, int n_tok, int n_warps)
{
    const int gtid = blockIdx.x * blockDim.x + threadIdx.x;
    const int w    = gtid >> 5;
    if (w >= n_warps) return;
    const int lane = gtid & 31;
    const int d0   = lane << 2;            // channels [d0, d0+4)

    const int tok0 = w * X_PER;            // X_PER tokens, same (f,y) row
    const int f    = tok0 / GRID_HW;
    const int rem  = tok0 - f * GRID_HW;
    const int y    = rem / GRID_W;

    const int video_pp = __ldg(nvf_p);
    const int pt = (f < video_pp) ? f : FIXED_REF;

    const int tbase = pt * T_DIM;
    const int hbase = y * H_DIM - T_DIM;
    const int wbase = (rem - y * GRID_W) * W_DIM - (T_DIM + H_DIM);

    const float* pc[2];
    const float* ps[2];
    bool   isw[2];
    float2 c[2], s[2];
#pragma unroll
    for (int h = 0; h < 2; h++) {
        const int d = d0 + 2 * h;          // even; pair (d,d+1) in one table
        if (d < T_DIM)              { pc[h] = tcos + tbase + d; ps[h] = tsin + tbase + d; isw[h] = false; }
        else if (d < T_DIM + H_DIM) { pc[h] = hcos + hbase + d; ps[h] = hsin + hbase + d; isw[h] = false; }
        else                        { pc[h] = wcos + wbase + d; ps[h] = wsin + wbase + d; isw[h] = true;  }
        c[h] = __ldg(reinterpret_cast<const float2*>(pc[h]));
        s[h] = __ldg(reinterpret_cast<const float2*>(ps[h]));
    }

    float* oc = out + (size_t)tok0 * 128 + d0;
    float* os = oc + (size_t)n_tok * 128;

#pragma unroll
    for (int xi = 0; xi < X_PER; xi++) {
        if (xi) {
#pragma unroll
            for (int h = 0; h < 2; h++) {
                if (isw[h]) {              // predicated: only w-lanes reload
                    pc[h] += W_DIM;  ps[h] += W_DIM;
                    c[h] = __ldg(reinterpret_cast<const float2*>(pc[h]));
                    s[h] = __ldg(reinterpret_cast<const float2*>(ps[h]));
                }
            }
        }
        *reinterpret_cast<float4*>(oc) = make_float4(c[0].x, c[0].y, c[1].x, c[1].y);
        *reinterpret_cast<float4*>(os) = make_float4(s[0].x, s[0].y, s[1].x, s[1].y);
        oc += 128;  os += 128;
    }
}

extern "C" void kernel_launch(void* const* d_in, const int* in_sizes, int n_in,
                              void* d_out, int out_size)
{
    // 0: hidden_states (unused)
    // 1: freq_t_cos  2: freq_h_cos  3: freq_w_cos
    // 4: freq_t_sin  5: freq_h_sin  6: freq_w_sin
    // 7: num_video_frames (int32)   8: num_ref_frames (int32)
    const float* tcos = (const float*)d_in[1];
    const float* hcos = (const float*)d_in[2];
    const float* wcos = (const float*)d_in[3];
    const float* tsin = (const float*)d_in[4];
    const float* hsin = (const float*)d_in[5];
    const float* wsin = (const float*)d_in[6];
    const int*   nvf  = (const int*)d_in[7];

    float* out = (float*)d_out;

    const int n_tok   = out_size / 256;    // out_size = 2 * n_tok * 128
    const int n_warps = n_tok / X_PER;     // n_tok = F*3600, divisible by X_PER
    const int threads = 256;
    const int blocks  = (n_warps * 32 + threads - 1) / threads;

    wan_rope_kernel<<<blocks, threads>>>(tcos, hcos, wcos, tsin, hsin, wsin,
                                         nvf, out, n_tok, n_warps);
}